// round 17
// baseline (speedup 1.0000x reference)
#include <cuda_runtime.h>

#define FULLMASK 0xffffffffu

// Problem dims (fixed by the dataset)
#define Bb 16
#define Ss 256
#define Nn 16
#define Dd 6

// Per-row projection partials, layout [row][hq*6 + d] = 6.3 MB
__device__ float g_part[(size_t)256 * 256 * 24];

// ---- Clifford sign machinery (5-bit blade masks, matches reference) ----
__host__ __device__ constexpr unsigned popc5(unsigned v) {
    v &= 31u;
    return (v & 1u) + ((v >> 1) & 1u) + ((v >> 2) & 1u) + ((v >> 3) & 1u) + ((v >> 4) & 1u);
}
__host__ __device__ constexpr int csn(unsigned a, unsigned b) {
    a >>= 1; int s = 0;
    while (a) { s += (int)popc5(a & b); a >>= 1; }
    return s & 1;
}
__host__ __device__ constexpr unsigned lift4(unsigned L) {
    L &= 15u;
    unsigned p = (L ^ (L >> 1) ^ (L >> 2) ^ (L >> 3)) & 1u;
    return L | (p << 4);
}
// quaternion unit product sign: dims XOR; neg iff bit(d1*4+d2) of 0xC6A0
#define QNEG(d1, d2) ((0xC6A0u >> ((d1) * 4 + (d2))) & 1u)

// ---- packed f32x2 helpers ----
__device__ __forceinline__ unsigned long long pk2(float lo, float hi) {
    unsigned long long r;
    asm("mov.b64 %0, {%1, %2};" : "=l"(r) : "f"(lo), "f"(hi));
    return r;
}
__device__ __forceinline__ void upk2(float& lo, float& hi, unsigned long long v) {
    asm("mov.b64 {%0, %1}, %2;" : "=f"(lo), "=f"(hi) : "l"(v));
}
#define FMA2(d, a, b, c) \
    asm("fma.rn.f32x2 %0, %1, %2, %3;" : "=l"(d) : "l"(a), "l"(b), "l"(c))
#define MUL2(d, a, b) \
    asm("mul.rn.f32x2 %0, %1, %2;" : "=l"(d) : "l"(a), "l"(b))

// ---------------------------------------------------------------------------
// Rotor recurrence + fused projection, M2(H) representation of each ideal.
// ONE WARP PER BLOCK (1024 blocks over 148 SMs).
// lane = h*8 + half*4 + q, q = r*2+c; each lane = one quaternion entry.
// R17: dl exchange via 4 SHFL.XOR + 8 ALU selects (one GP operand is always
// the LOCAL dl) -> 4 fewer MIO ops per step on the contended crossbar.
// Carrier unnormalized (dl scaled by stale rn_{t-2}); normalization applied
// as output scale only.
// ---------------------------------------------------------------------------
__global__ void __launch_bounds__(32) rotor_rnn_kernel(
    const float* __restrict__ x,      // [B,S,N,D]
    const float* __restrict__ W_in,   // [D, H*32]
    const float* __restrict__ b_in,   // [H*32]
    const float* __restrict__ W_out)  // [H*32, D]
{
    __shared__ float sR[2][32][9];    // partials + s, 9-float rows (bank-safe)

    const int gw   = blockIdx.x;          // 0..1023
    const int lane = threadIdx.x & 31;
    const int c  = gw >> 2;                // chain 0..255
    const int hq = gw & 3;                 // head quad
    const int h    = hq * 4 + (lane >> 3);
    const int half = (lane >> 2) & 1;      // ideal half
    const int r    = (lane >> 1) & 1;      // matrix row
    const int cl   = lane & 1;             // matrix col
    const int b  = c >> 4;
    const int n  = c & (Nn - 1);
    const int gg = lane & 7;
    const int hb = lane & 24;              // head's lane base

    // ======== one-time init: weights in matrix coordinates ========
    float wi[4][Dd], bi[4], wo[4][Dd];
#pragma unroll
    for (int k = 0; k < 4; ++k) {
        bi[k] = 0.f;
#pragma unroll
        for (int d = 0; d < Dd; ++d) { wi[k][d] = 0.f; wo[k][d] = 0.f; }
    }

#pragma unroll
    for (int L = 0; L < 16; ++L) {
        // --- build rho(b_L): pat/dA/dB/sA/sB/sgn all compile-time ---
        int pat = 0, dA = 0, dB = 0, sA = 1, sB = 1, sgn = 0;
        unsigned cur = 0;
#pragma unroll
        for (int i = 0; i < 4; ++i) {
            if ((L >> i) & 1) {
                const unsigned fm = (1u << i) | 0x10u;   // f_{i+1} = e_{i+1} e_5
                sgn ^= csn(cur, fm);
                cur ^= fm;
                const int gd  = i;
                const int gAs = 1, gBs = (i == 0) ? -1 : 1;
                if (pat == 0) {
                    sA *= gAs * (QNEG(dA, gd) ? -1 : 1); dA ^= gd;
                    sB *= gBs * (QNEG(dB, gd) ? -1 : 1); dB ^= gd;
                    pat = 1;
                } else {
                    sA *= gBs * (QNEG(dA, gd) ? -1 : 1); dA ^= gd;
                    sB *= gAs * (QNEG(dB, gd) ? -1 : 1); dB ^= gd;
                    pat = 0;
                }
            }
        }
        const float mine = (((pat == 0) == (r == cl)) ? 1.f : 0.f);
        const float sAf = (float)(sA * (sgn ? -1 : 1));
        const float sBf = (float)(sB * (sgn ? -1 : 1));
        const float fA = (r == 0) ? mine * sAf : 0.f;
        const float fB = (r == 1) ? mine * sBf : 0.f;

        // --- omega-split (half) transform ---
        const unsigned E  = lift4((unsigned)L);
        const unsigned Ed = E ^ 31u;
        const float sIn  = csn(31u, Ed) ? -1.f : 1.f;
        const float sOut = csn(31u, E)  ? -1.f : 1.f;
        const float cIn  = half ? -sIn  : sIn;
        const float cOut = half ? -sOut : sOut;
        const int colE = h * 32 + (int)E;
        const int colD = h * 32 + (int)Ed;

#pragma unroll
        for (int d = 0; d < Dd; ++d) {
            const float vin  = __ldg(W_in + d * 512 + colE) +
                               cIn  * __ldg(W_in + d * 512 + colD);
            const float vout = 0.5f * (__ldg(W_out + colE * Dd + d) +
                               cOut * __ldg(W_out + colD * Dd + d));
            wi[dA][d] = fmaf(fA, vin,  wi[dA][d]);
            wi[dB][d] = fmaf(fB, vin,  wi[dB][d]);
            wo[dA][d] = fmaf(fA, vout, wo[dA][d]);
            wo[dB][d] = fmaf(fB, vout, wo[dB][d]);
        }
        const float vb = __ldg(b_in + colE) + cIn * __ldg(b_in + colD);
        bi[dA] = fmaf(fA, vb, bi[dA]);
        bi[dB] = fmaf(fB, vb, bi[dB]);
    }
    // per-step "+1 on scalar blade" folded into bias: rho(1) = I
    if (r == cl) bi[0] += 1.0f;

    // packed weights: input (pairs 01 / 23) and output
    unsigned long long wiP01[Dd], wiP23[Dd];
#pragma unroll
    for (int d = 0; d < Dd; ++d) {
        wiP01[d] = pk2(wi[0][d], wi[1][d]);
        wiP23[d] = pk2(wi[2][d], wi[3][d]);
    }
    const unsigned long long biP01 = pk2(bi[0], bi[1]);
    const unsigned long long biP23 = pk2(bi[2], bi[3]);
    unsigned long long woP[4][3];
#pragma unroll
    for (int k = 0; k < 4; ++k)
#pragma unroll
        for (int j = 0; j < 3; ++j)
            woP[k][j] = pk2(wo[k][2 * j], wo[k][2 * j + 1]);

    // operand routing: one GP operand is LOCAL dl, the other is lane^1's.
    // diagb = 0 (r==c): a = local, bq = neighbor; diagb = 1: swapped.
    const bool swapAB = (((lane >> 1) ^ lane) & 1) != 0;
    const int laneS = hb | 6;                     // lane holding head's s-sum

    // carrier init: 0.5 * Identity per half (psi0 = scalar 1)
    float m0 = (r == cl) ? 0.5f : 0.f, m1 = 0.f, m2 = 0.f, m3 = 0.f;
    float rnA = 1.0f, rnB = 1.0f;

    const float2* xp = (const float2*)(x + ((size_t)(b * Ss) * Nn + n) * Dd);
    float* pw = g_part + ((size_t)c * Ss) * 24 + hq * 6 + lane;

    float2 cx01 = __ldg(xp + 0), cx23 = __ldg(xp + 1), cx45 = __ldg(xp + 2);

#pragma unroll 2
    for (int t = 0; t < Ss; ++t) {
        const int buf = t & 1;

        // prefetch next x (3x LDG.64, warp-uniform)
        const float2* xn = xp + (Nn * Dd) / 2;
        float2 n01, n23, n45;
        if (t + 1 < Ss) {
            n01 = __ldg(xn + 0); n23 = __ldg(xn + 1); n45 = __ldg(xn + 2);
        } else {
            n01 = make_float2(0.f, 0.f); n23 = n01; n45 = n01;
        }

        // dl (packed f32x2), scaled by stale rn_{t-2}
        unsigned long long d01 = biP01, d23 = biP23;
        {
            const float xs[6] = {cx01.x, cx01.y, cx23.x, cx23.y, cx45.x, cx45.y};
#pragma unroll
            for (int dd = 0; dd < Dd; ++dd) {
                const unsigned long long xb = pk2(xs[dd], xs[dd]);
                FMA2(d01, xb, wiP01[dd], d01);
                FMA2(d23, xb, wiP23[dd], d23);
            }
            const unsigned long long rp = pk2(rnA, rnA);
            MUL2(d01, d01, rp);
            MUL2(d23, d23, rp);
        }
        float d0, d1, d2, d3;
        upk2(d0, d1, d01);
        upk2(d2, d3, d23);

        // neighbor dl via 4 SHFL.XOR; route (a, bq) with ALU selects
        float4 v;
        v.x = __shfl_xor_sync(FULLMASK, d0, 1);
        v.y = __shfl_xor_sync(FULLMASK, d1, 1);
        v.z = __shfl_xor_sync(FULLMASK, d2, 1);
        v.w = __shfl_xor_sync(FULLMASK, d3, 1);
        float4 a, bq;
        a.x  = swapAB ? v.x : d0;  bq.x = swapAB ? d0 : v.x;
        a.y  = swapAB ? v.y : d1;  bq.y = swapAB ? d1 : v.y;
        a.z  = swapAB ? v.z : d2;  bq.z = swapAB ? d2 : v.z;
        a.w  = swapAB ? v.w : d3;  bq.w = swapAB ? d3 : v.w;
        // carrier neighbor w[r^1][c] via shuffle
        float4 wn;
        wn.x = __shfl_xor_sync(FULLMASK, m0, 2);
        wn.y = __shfl_xor_sync(FULLMASK, m1, 2);
        wn.z = __shfl_xor_sync(FULLMASK, m2, 2);
        wn.w = __shfl_xor_sync(FULLMASK, m3, 2);

        // M_new[r][c] = a (x) w_local + bq (x) wn  (quaternion products)
        float qa0, qa1, qa2, qa3, qb0, qb1, qb2, qb3;
        qa0 =        a.x * m0;
        qa0 = fmaf(-a.y, m1, qa0); qa0 = fmaf(-a.z, m2, qa0); qa0 = fmaf(-a.w, m3, qa0);
        qa1 =        a.x * m1;
        qa1 = fmaf( a.y, m0, qa1); qa1 = fmaf( a.z, m3, qa1); qa1 = fmaf(-a.w, m2, qa1);
        qa2 =        a.x * m2;
        qa2 = fmaf(-a.y, m3, qa2); qa2 = fmaf( a.z, m0, qa2); qa2 = fmaf( a.w, m1, qa2);
        qa3 =        a.x * m3;
        qa3 = fmaf( a.y, m2, qa3); qa3 = fmaf(-a.z, m1, qa3); qa3 = fmaf( a.w, m0, qa3);

        qb0 =        bq.x * wn.x;
        qb0 = fmaf(-bq.y, wn.y, qb0); qb0 = fmaf(-bq.z, wn.z, qb0); qb0 = fmaf(-bq.w, wn.w, qb0);
        qb1 =        bq.x * wn.y;
        qb1 = fmaf( bq.y, wn.x, qb1); qb1 = fmaf( bq.z, wn.w, qb1); qb1 = fmaf(-bq.w, wn.z, qb1);
        qb2 =        bq.x * wn.z;
        qb2 = fmaf(-bq.y, wn.w, qb2); qb2 = fmaf( bq.z, wn.x, qb2); qb2 = fmaf( bq.w, wn.y, qb2);
        qb3 =        bq.x * wn.w;
        qb3 = fmaf( bq.y, wn.z, qb3); qb3 = fmaf(-bq.z, wn.y, qb3); qb3 = fmaf( bq.w, wn.x, qb3);

        const float nw0 = qa0 + qb0, nw1 = qa1 + qb1;
        const float nw2 = qa2 + qb2, nw3 = qa3 + qb3;

        // local squared-norm contribution (reduced via the smem transpose)
        float sl = nw0 * nw0 + nw1 * nw1;
        sl = fmaf(nw2, nw2, sl);
        sl = fmaf(nw3, nw3, sl);

        // ---- projection partials on RAW nw, packed f32x2 ----
        const unsigned long long w0p = pk2(nw0, nw0);
        const unsigned long long w1p = pk2(nw1, nw1);
        const unsigned long long w2p = pk2(nw2, nw2);
        const unsigned long long w3p = pk2(nw3, nw3);
        unsigned long long p01, p23, p45;
        MUL2(p01, w0p, woP[0][0]);
        MUL2(p23, w0p, woP[0][1]);
        MUL2(p45, w0p, woP[0][2]);
        FMA2(p01, w1p, woP[1][0], p01);
        FMA2(p23, w1p, woP[1][1], p23);
        FMA2(p45, w1p, woP[1][2], p45);
        FMA2(p01, w2p, woP[2][0], p01);
        FMA2(p23, w2p, woP[2][1], p23);
        FMA2(p45, w2p, woP[2][2], p45);
        FMA2(p01, w3p, woP[3][0], p01);
        FMA2(p23, w3p, woP[3][1], p23);
        FMA2(p45, w3p, woP[3][2], p45);

        // store partials + s (7x STS.32, stride-9 rows: conflict-free)
        float f0, f1, f2, f3, f4, f5;
        upk2(f0, f1, p01);
        upk2(f2, f3, p23);
        upk2(f4, f5, p45);
        float* rrow = &sR[buf][lane][0];
        rrow[0] = f0; rrow[1] = f1; rrow[2] = f2;
        rrow[3] = f3; rrow[4] = f4; rrow[5] = f5;
        rrow[6] = sl;
        __syncwarp();

        // transpose-reduce: bank = (hb + 9k + gg) % 32 -> conflict-free
        float acc = sR[buf][hb | 0][gg];
        acc += sR[buf][hb | 1][gg];
        acc += sR[buf][hb | 2][gg];
        acc += sR[buf][hb | 3][gg];
        acc += sR[buf][hb | 4][gg];
        acc += sR[buf][hb | 5][gg];
        acc += sR[buf][hb | 6][gg];
        acc += sR[buf][hb | 7][gg];
        // head norm total rides column 6
        const float sTot = __shfl_sync(FULLMASK, acc, laneS);
        const float rn = rsqrtf(sTot + 1e-12f);   // output-scale only

        // scale by own head's rn, then sum the quad's 4 heads in-warp
        float p = acc * rn;
        p += __shfl_xor_sync(FULLMASK, p, 8);
        p += __shfl_xor_sync(FULLMASK, p, 16);
        if (lane < 6) *pw = p;
        pw += 24;

        // rotate state / scales / inputs
        m0 = nw0; m1 = nw1; m2 = nw2; m3 = nw3;
        rnA = rnB; rnB = rn;
        xp = xn;
        cx01 = n01; cx23 = n23; cx45 = n45;
    }
}

// ---------------------------------------------------------------------------
// Combine: y[row,d] = x[row,d] + b_out[d] + sum_{4 hq} g_part[row][hq*6+d]
// ---------------------------------------------------------------------------
__global__ void __launch_bounds__(256) combine_kernel(
    const float* __restrict__ x,
    const float* __restrict__ b_out,
    float* __restrict__ y)
{
    const int e   = blockIdx.x * blockDim.x + threadIdx.x;  // 0..393215
    const int row = e / 6;              // chain*256 + t
    const int d   = e - row * 6;

    const float* pp = g_part + (size_t)row * 24 + d;
    float acc = __ldg(b_out + d)
              + (__ldg(pp) + __ldg(pp + 6)) + (__ldg(pp + 12) + __ldg(pp + 18));

    const int c = row >> 8;
    const int t = row & (Ss - 1);
    const int b = c >> 4;
    const int n = c & (Nn - 1);
    const size_t off = (((size_t)b * Ss + t) * Nn + n) * Dd + d;
    y[off] = __ldg(x + off) + acc;
}

extern "C" void kernel_launch(void* const* d_in, const int* in_sizes, int n_in,
                              void* d_out, int out_size) {
    const float* x     = (const float*)d_in[0];
    const float* W_in  = (const float*)d_in[1];
    const float* b_in  = (const float*)d_in[2];
    const float* W_out = (const float*)d_in[3];
    const float* b_out = (const float*)d_in[4];
    float* y = (float*)d_out;

    // Phase 1: 1024 one-warp blocks (load-balanced across all 148 SMs)
    rotor_rnn_kernel<<<1024, 32>>>(x, W_in, b_in, W_out);
    // Phase 2: combine (65536 rows x 6)
    combine_kernel<<<1536, 256>>>(x, b_out, y);
}